// round 14
// baseline (speedup 1.0000x reference)
#include <cuda_runtime.h>
#include <cuda_fp16.h>
#include <math.h>

#define NN 50000
#define EE 800000
#define ETOT (EE + NN)
#define DIM 128
#define HH 4
#define CC 32
#define NEG_SLOPE 0.2f
#define GRID 444            // 3 blocks per SM on 148+ SMs; co-residency guaranteed
#define TPB 256
#define NSEG 113            // ceil(NN / GRID)

// ---------------- device scratch (no allocations allowed) ----------------
__device__ int     g_count[NN];
__device__ int     g_rowptr[NN + 1];
__device__ int     g_cursor[NN];
__device__ int     g_colidx[ETOT];
__device__ float   g_h[NN * DIM];          // activated layer input, fp32
__device__ __half2 g_hwh[NN * (DIM / 2)];  // transformed features, fp16 gather array
__device__ float   g_asrc[NN * HH];
__device__ float   g_adst[NN * HH];
__device__ float2  g_Wp1[(DIM / 2) * DIM];
__device__ float2  g_Wp2[(DIM / 2) * DIM];
__device__ float2  g_Wp3[(DIM / 2) * CC];
__device__ int     g_btot[GRID];
__device__ unsigned         g_cnt;   // zero-initialized; barrier leaves it at 0
__device__ volatile unsigned g_gen;  // monotonically increasing generation

// Sense-reversing grid barrier. __threadfence (gpu scope) emits CCTL.IVALL on
// sm_103a -> also invalidates this SM's L1D, giving cross-phase coherence for
// re-read arrays (g_h, g_hwh, g_asrc, g_adst) in this persistent kernel.
__device__ __forceinline__ void gbar() {
    __syncthreads();
    if (threadIdx.x == 0) {
        __threadfence();                       // release + L1 flush
        unsigned my = g_gen;
        if (atomicAdd(&g_cnt, 1u) == (unsigned)(GRID - 1)) {
            g_cnt = 0u;
            __threadfence();
            g_gen = my + 1u;
        } else {
            while (g_gen == my) __nanosleep(32);
        }
        __threadfence();                       // acquire + L1 flush
    }
    __syncthreads();
}

__device__ __forceinline__ void ffma2(unsigned long long& d,
                                      unsigned long long a, unsigned long long b) {
    asm("fma.rn.f32x2 %0, %1, %2, %0;" : "+l"(d) : "l"(a), "l"(b));
}

// ---------------- GEMM phase (persistent tile loop), R=4, 8 warps ----------
template <int FOUT, int HEADS, bool USE_GH>
__device__ void d_gemm(const float* __restrict__ Xin, const float2* __restrict__ Wp,
                       const float* __restrict__ a_s, const float* __restrict__ a_d,
                       float4 (*xs)[4][DIM / 4], int tid) {
    const int R = 4;
    const int NC = FOUT / 32;
    int lane = tid & 31, wip = tid >> 5;
    const float* __restrict__ X = USE_GH ? (const float*)g_h : Xin;
    __half* __restrict__ hw16 = reinterpret_cast<__half*>(g_hwh);

    float asv[NC], adv[NC];
    #pragma unroll
    for (int c = 0; c < NC; c++) {
        asv[c] = a_s[c * 32 + lane];
        adv[c] = a_d[c * 32 + lane];
    }

    const int ntiles = (NN + 31) / 32;
    for (int tb = blockIdx.x; tb < ntiles; tb += GRID) {
        int base = tb * 32 + wip * 4;
        #pragma unroll
        for (int r = 0; r < R; r++) {
            int row = base + r;
            float4 v = make_float4(0.f, 0.f, 0.f, 0.f);
            if (row < NN) v = reinterpret_cast<const float4*>(X + (size_t)row * DIM)[lane];
            xs[wip][r][lane] = v;
        }
        __syncwarp();

        unsigned long long acc[R][NC];
        #pragma unroll
        for (int r = 0; r < R; r++)
            #pragma unroll
            for (int c = 0; c < NC; c++) acc[r][c] = 0ull;

        #pragma unroll 4
        for (int k4 = 0; k4 < DIM / 4; k4++) {
            unsigned long long wA[NC], wB[NC];
            #pragma unroll
            for (int c = 0; c < NC; c++) {
                wA[c] = *reinterpret_cast<const unsigned long long*>(
                            &Wp[(2 * k4) * FOUT + c * 32 + lane]);
                wB[c] = *reinterpret_cast<const unsigned long long*>(
                            &Wp[(2 * k4 + 1) * FOUT + c * 32 + lane]);
            }
            #pragma unroll
            for (int r = 0; r < R; r++) {
                ulonglong2 xv = reinterpret_cast<const ulonglong2*>(&xs[wip][r][0])[k4];
                #pragma unroll
                for (int c = 0; c < NC; c++) {
                    ffma2(acc[r][c], wA[c], xv.x);
                    ffma2(acc[r][c], wB[c], xv.y);
                }
            }
        }

        #pragma unroll
        for (int r = 0; r < R; r++) {
            int row = base + r;
            #pragma unroll
            for (int c = 0; c < NC; c++) {
                unsigned long long a = acc[r][c];
                float h = __uint_as_float((unsigned)(a & 0xffffffffull)) +
                          __uint_as_float((unsigned)(a >> 32));
                if (row < NN) hw16[(size_t)row * FOUT + c * 32 + lane] = __float2half_rn(h);
                float vs = h * asv[c], vd = h * adv[c];
                #pragma unroll
                for (int off = 16; off; off >>= 1) {
                    vs += __shfl_xor_sync(0xffffffffu, vs, off);
                    vd += __shfl_xor_sync(0xffffffffu, vd, off);
                }
                if (lane == 0 && row < NN) {
                    g_asrc[row * HEADS + c] = vs;
                    g_adst[row * HEADS + c] = vd;
                }
            }
        }
        __syncwarp();   // all lanes done reading xs before next tile overwrites
    }
}

// ---------------- agg4: one warp per dst, all 4 heads (grid-stride) --------
__device__ void d_agg4(const float* __restrict__ bias, int tid) {
    int wip = tid >> 5, lane = tid & 31;
    int sub = lane & 3, ej = lane >> 2, myhead = lane >> 3;
    const __half2* __restrict__ hp = g_hwh;

    for (int dst = blockIdx.x * 8 + wip; dst < NN; dst += GRID * 8) {
        float adv = g_adst[dst * HH + sub];
        int p0 = g_rowptr[dst], p1 = g_rowptr[dst + 1];

        float4 acc = make_float4(0.f, 0.f, 0.f, 0.f);
        float ssum = 0.f;

        for (int b = p0; b < p1; b += 8) {
            int p = b + ej;
            bool valid = (p < p1);
            int src = g_colidx[valid ? p : (p1 - 1)];
            float t = g_asrc[src * HH + sub] + adv;
            t = (t >= 0.f) ? t : NEG_SLOPE * t;
            float e = valid ? __expf(t) : 0.f;
            int offs = src * (DIM / 2);
            ssum += e;

            float w[8]; int o[8];
            #pragma unroll
            for (int j = 0; j < 8; j++) {
                w[j] = __shfl_sync(0xffffffffu, e, j * 4 + myhead);
                o[j] = __shfl_sync(0xffffffffu, offs, j * 4);
            }
            #pragma unroll
            for (int j = 0; j < 8; j++) {
                uint2 raw = *reinterpret_cast<const uint2*>(hp + o[j] + lane * 2);
                float2 f0 = __half22float2(*reinterpret_cast<__half2*>(&raw.x));
                float2 f1 = __half22float2(*reinterpret_cast<__half2*>(&raw.y));
                acc.x += w[j] * f0.x; acc.y += w[j] * f0.y;
                acc.z += w[j] * f1.x; acc.w += w[j] * f1.y;
            }
        }
        ssum += __shfl_xor_sync(0xffffffffu, ssum, 4);
        ssum += __shfl_xor_sync(0xffffffffu, ssum, 8);
        ssum += __shfl_xor_sync(0xffffffffu, ssum, 16);
        float s = __shfl_sync(0xffffffffu, ssum, myhead);
        float inv = 1.f / (s + 1e-16f);

        float4 bb = *reinterpret_cast<const float4*>(bias + lane * 4);
        float4 o4;
        o4.x = acc.x * inv + bb.x;
        o4.y = acc.y * inv + bb.y;
        o4.z = acc.z * inv + bb.z;
        o4.w = acc.w * inv + bb.w;
        o4.x = (o4.x > 0.f) ? o4.x : expm1f(o4.x);
        o4.y = (o4.y > 0.f) ? o4.y : expm1f(o4.y);
        o4.z = (o4.z > 0.f) ? o4.z : expm1f(o4.z);
        o4.w = (o4.w > 0.f) ? o4.w : expm1f(o4.w);
        *reinterpret_cast<float4*>(g_h + dst * DIM + lane * 4) = o4;
    }
}

// ---------------- agg1: warp per dst, single head (grid-stride) ------------
__device__ void d_agg1(const float* __restrict__ bias, float* __restrict__ OUT, int tid) {
    int wip = tid >> 5, lane = tid & 31;
    const __half* __restrict__ hw16 = reinterpret_cast<const __half*>(g_hwh);

    for (int dst = blockIdx.x * 8 + wip; dst < NN; dst += GRID * 8) {
        float adv = g_adst[dst];
        int p0 = g_rowptr[dst], p1 = g_rowptr[dst + 1];

        float ssum = 0.f, acc = 0.f;
        for (int b = p0; b < p1; b += 32) {
            int p = b + lane;
            bool valid = (p < p1);
            int src = g_colidx[valid ? p : (p1 - 1)];
            float t = g_asrc[src] + adv;
            t = (t >= 0.f) ? t : NEG_SLOPE * t;
            float e = valid ? __expf(t) : 0.f;
            int offs = src * CC;
            ssum += e;

            int cnt = min(32, p1 - b);
            #pragma unroll
            for (int g = 0; g < 4; g++) {
                if (g * 8 >= cnt) break;        // uniform across warp
                float w[8]; int o[8];
                #pragma unroll
                for (int j = 0; j < 8; j++) {
                    w[j] = __shfl_sync(0xffffffffu, e, g * 8 + j);
                    o[j] = __shfl_sync(0xffffffffu, offs, g * 8 + j);
                }
                #pragma unroll
                for (int j = 0; j < 8; j++)
                    acc += w[j] * __half2float(hw16[o[j] + lane]);
            }
        }
        float s = ssum;
        #pragma unroll
        for (int off = 16; off; off >>= 1)
            s += __shfl_xor_sync(0xffffffffu, s, off);

        OUT[dst * CC + lane] = acc / (s + 1e-16f) + bias[lane];
    }
}

// ---------------- the mega-kernel ----------------
__global__ void __launch_bounds__(TPB, 3) k_mega(
    const float* __restrict__ x,  const int* __restrict__ ei,
    const float* __restrict__ W1, const float* __restrict__ as1,
    const float* __restrict__ ad1, const float* __restrict__ b1,
    const float* __restrict__ W2, const float* __restrict__ as2,
    const float* __restrict__ ad2, const float* __restrict__ b2,
    const float* __restrict__ W3, const float* __restrict__ as3,
    const float* __restrict__ ad3, const float* __restrict__ b3,
    float* __restrict__ out) {
    __shared__ float4 xs[8][4][DIM / 4];   // 16 KB, gemm staging
    __shared__ int s_scan[128];
    __shared__ int s_red[8];
    int tid = threadIdx.x;
    int gstep = GRID * TPB;
    int gid = blockIdx.x * TPB + tid;

    // ---- P0: zero counts + pack all weights ----
    for (int i = gid; i < NN; i += gstep) g_count[i] = 0;
    for (int i = gid; i < (DIM / 2) * DIM + (DIM / 2) * CC; i += gstep) {
        if (i < (DIM / 2) * DIM) {
            int k2 = i / DIM, j = i - k2 * DIM;
            g_Wp1[i] = make_float2(W1[(2 * k2) * DIM + j], W1[(2 * k2 + 1) * DIM + j]);
            g_Wp2[i] = make_float2(W2[(2 * k2) * DIM + j], W2[(2 * k2 + 1) * DIM + j]);
        } else {
            int t = i - (DIM / 2) * DIM;
            int k2 = t / CC, j = t - k2 * CC;
            g_Wp3[t] = make_float2(W3[(2 * k2) * CC + j], W3[(2 * k2 + 1) * CC + j]);
        }
    }
    gbar();

    // ---- P1: GEMM layer 1 (no CSR dependency) + edge counting, overlapped ----
    d_gemm<DIM, HH, false>(x, g_Wp1, as1, ad1, xs, tid);
    for (int e = gid; e < EE; e += gstep) atomicAdd(&g_count[ei[EE + e]], 1);
    gbar();

    // ---- P2: per-block segment totals (+1 folds in self loop) ----
    {
        int s0 = blockIdx.x * NSEG;
        int s1 = min(NN, s0 + NSEG);
        int v = 0;
        for (int i = s0 + tid; i < s1; i += TPB) v += g_count[i] + 1;
        #pragma unroll
        for (int o = 16; o; o >>= 1) v += __shfl_xor_sync(0xffffffffu, v, o);
        if ((tid & 31) == 0) s_red[tid >> 5] = v;
        __syncthreads();
        if (tid == 0) {
            int t = 0;
            #pragma unroll
            for (int w = 0; w < 8; w++) t += s_red[w];
            g_btot[blockIdx.x] = t;
        }
    }
    gbar();

    // ---- P3: own offset (sum of earlier block totals) + local scan ----
    {
        int off = 0;
        for (int i = tid; i < blockIdx.x; i += TPB) off += g_btot[i];
        #pragma unroll
        for (int o = 16; o; o >>= 1) off += __shfl_xor_sync(0xffffffffu, off, o);
        if ((tid & 31) == 0) s_red[tid >> 5] = off;
        __syncthreads();
        int basev = 0;
        #pragma unroll
        for (int w = 0; w < 8; w++) basev += s_red[w];

        int s0 = blockIdx.x * NSEG;
        int val = 0;
        if (tid < 128) {
            int i = s0 + tid;
            val = (tid < NSEG && i < NN) ? g_count[i] + 1 : 0;
            s_scan[tid] = val;
        }
        __syncthreads();
        for (int d = 1; d < 128; d <<= 1) {
            int add = 0;
            if (tid < 128 && tid >= d) add = s_scan[tid - d];
            __syncthreads();
            if (tid < 128) s_scan[tid] += add;
            __syncthreads();
        }
        if (tid < NSEG) {
            int i = s0 + tid;
            if (i < NN) {
                int excl = basev + s_scan[tid] - val;   // exclusive prefix
                g_rowptr[i] = excl;
                g_cursor[i] = excl;
            }
        }
        if (blockIdx.x == 0 && tid == 0) g_rowptr[NN] = ETOT;
    }
    gbar();

    // ---- P4: fill CSR (edges + self loops) ----
    for (int e = gid; e < ETOT; e += gstep) {
        if (e < EE) {
            int d = ei[EE + e];
            int pos = atomicAdd(&g_cursor[d], 1);
            g_colidx[pos] = ei[e];
        } else {
            int i = e - EE;
            int pos = atomicAdd(&g_cursor[i], 1);
            g_colidx[pos] = i;
        }
    }
    gbar();

    // ---- P5: aggregate layer 1 ----
    d_agg4(b1, tid);
    gbar();

    // ---- P6: GEMM layer 2 ----
    d_gemm<DIM, HH, true>(nullptr, g_Wp2, as2, ad2, xs, tid);
    gbar();

    // ---- P7: aggregate layer 2 ----
    d_agg4(b2, tid);
    gbar();

    // ---- P8: GEMM layer 3 ----
    d_gemm<CC, 1, true>(nullptr, g_Wp3, as3, ad3, xs, tid);
    gbar();

    // ---- P9: aggregate layer 3 -> output ----
    d_agg1(b3, out, tid);
}

// ---------------- launch ----------------
extern "C" void kernel_launch(void* const* d_in, const int* in_sizes, int n_in,
                              void* d_out, int out_size) {
    const float* x   = (const float*)d_in[0];
    const int*   ei  = (const int*)  d_in[1];
    const float* W1  = (const float*)d_in[2];
    const float* as1 = (const float*)d_in[3];
    const float* ad1 = (const float*)d_in[4];
    const float* b1  = (const float*)d_in[5];
    const float* W2  = (const float*)d_in[6];
    const float* as2 = (const float*)d_in[7];
    const float* ad2 = (const float*)d_in[8];
    const float* b2  = (const float*)d_in[9];
    const float* W3  = (const float*)d_in[10];
    const float* as3 = (const float*)d_in[11];
    const float* ad3 = (const float*)d_in[12];
    const float* b3  = (const float*)d_in[13];
    float* out = (float*)d_out;

    k_mega<<<GRID, TPB>>>(x, ei, W1, as1, ad1, b1, W2, as2, ad2, b2,
                          W3, as3, ad3, b3, out);
}

// round 16
// speedup vs baseline: 1.1567x; 1.1567x over previous
#include <cuda_runtime.h>
#include <cuda_fp16.h>
#include <math.h>

#define NN 50000
#define EE 800000
#define ETOT (EE + NN)
#define DIM 128
#define HH 4
#define CC 32
#define NEG_SLOPE 0.2f

// ---------------- device scratch (no allocations allowed) ----------------
__device__ int     g_count[NN];
__device__ int     g_rowptr[NN + 1];
__device__ int     g_cursor[NN];
__device__ int     g_colidx[ETOT];
__device__ float   g_h[NN * DIM];          // activated layer input, fp32
__device__ __half2 g_hwh[NN * (DIM / 2)];  // transformed features, fp16 gather array
__device__ float   g_asrc[NN * HH];
__device__ float   g_adst[NN * HH];
// fp16 K-quad packed weights: [k4*FOUT + j] = {h2(W[4k4][j],W[4k4+1][j]), h2(W[4k4+2][j],W[4k4+3][j])}
__device__ uint2   g_Wh1[(DIM / 4) * DIM];
__device__ uint2   g_Wh2[(DIM / 4) * DIM];
__device__ uint2   g_Wh3[(DIM / 4) * CC];

// ---------------- CSR build ----------------
__global__ void k_count(const int* __restrict__ ei) {
    int e = blockIdx.x * blockDim.x + threadIdx.x;
    if (e < EE) atomicAdd(&g_count[ei[EE + e]], 1);
}

// single-block shuffle-based exclusive scan (N=50000); +1 folds in self loop
__global__ void k_scan() {
    __shared__ int wsum[32];
    __shared__ int carry_s;
    int lane = threadIdx.x & 31;
    int wid  = threadIdx.x >> 5;
    if (threadIdx.x == 0) carry_s = 0;
    __syncthreads();
    for (int base = 0; base < NN; base += 1024) {
        int i = base + threadIdx.x;
        int v = (i < NN) ? (g_count[i] + 1) : 0;   // +1 = self loop
        int x = v;
        #pragma unroll
        for (int off = 1; off < 32; off <<= 1) {
            int t = __shfl_up_sync(0xffffffffu, x, off);
            if (lane >= off) x += t;
        }
        if (lane == 31) wsum[wid] = x;
        __syncthreads();
        if (wid == 0) {
            int y = wsum[lane];
            #pragma unroll
            for (int off = 1; off < 32; off <<= 1) {
                int t = __shfl_up_sync(0xffffffffu, y, off);
                if (lane >= off) y += t;
            }
            wsum[lane] = y;
        }
        __syncthreads();
        int wpre = (wid > 0) ? wsum[wid - 1] : 0;
        int excl = carry_s + wpre + x - v;
        if (i < NN) { g_rowptr[i] = excl; g_cursor[i] = excl; }
        int tot = wsum[31];
        __syncthreads();
        if (threadIdx.x == 0) carry_s += tot;
        __syncthreads();
    }
    if (threadIdx.x == 0) g_rowptr[NN] = carry_s;
}

__global__ void k_fill(const int* __restrict__ ei) {
    int e = blockIdx.x * blockDim.x + threadIdx.x;
    if (e < EE) {
        int d = ei[EE + e];
        int pos = atomicAdd(&g_cursor[d], 1);
        g_colidx[pos] = ei[e];
    } else if (e < EE + NN) {
        int i = e - EE;
        int pos = atomicAdd(&g_cursor[i], 1);
        g_colidx[pos] = i;    // self loop
    }
}

// ---------------- pack ALL weight matrices to fp16 K-quads (one launch) ----
__device__ __forceinline__ uint2 packquad(const float* W, int k4, int j, int FOUT) {
    __half2 lo = __floats2half2_rn(W[(4 * k4) * FOUT + j], W[(4 * k4 + 1) * FOUT + j]);
    __half2 hi = __floats2half2_rn(W[(4 * k4 + 2) * FOUT + j], W[(4 * k4 + 3) * FOUT + j]);
    uint2 r;
    r.x = *reinterpret_cast<unsigned*>(&lo);
    r.y = *reinterpret_cast<unsigned*>(&hi);
    return r;
}

__global__ void k_packAll(const float* __restrict__ W1, const float* __restrict__ W2,
                          const float* __restrict__ W3) {
    int i = blockIdx.x * blockDim.x + threadIdx.x;
    if (i < (DIM / 4) * DIM) {
        int k4 = i / DIM, j = i - k4 * DIM;
        g_Wh1[i] = packquad(W1, k4, j, DIM);
        g_Wh2[i] = packquad(W2, k4, j, DIM);
    } else {
        int t = i - (DIM / 4) * DIM;
        if (t < (DIM / 4) * CC) {
            int k4 = t / CC, j = t - k4 * CC;
            g_Wh3[t] = packquad(W3, k4, j, CC);
        }
    }
}

__device__ __forceinline__ void ffma2(unsigned long long& d,
                                      unsigned long long a, unsigned long long b) {
    asm("fma.rn.f32x2 %0, %1, %2, %0;" : "+l"(d) : "l"(a), "l"(b));
}

__device__ __forceinline__ unsigned long long f2_to_ull(float2 f) {
    unsigned long long u;
    asm("mov.b64 %0, {%1, %2};" : "=l"(u) : "f"(f.x), "f"(f.y));
    return u;
}

// ---------------- GEMM + attention-coefficient reduction ----------------
// fp32 math, fp16 weights (converted in registers); h stored fp16, logits fp32.
template <int FIN, int FOUT, int HEADS_T, bool USE_GH>
__global__ void k_gemm(const float* __restrict__ Xin, const uint2* __restrict__ Wh,
                       const float* __restrict__ a_s, const float* __restrict__ a_d) {
    const int R = 8;
    const int NC = FOUT / 32;
    __shared__ float4 xs[4][R][FIN / 4];
    int lane = threadIdx.x & 31, wip = threadIdx.x >> 5;
    int base = (blockIdx.x * 4 + wip) * R;
    const float* __restrict__ X = USE_GH ? (const float*)g_h : Xin;

    #pragma unroll
    for (int r = 0; r < R; r++) {
        int row = base + r;
        float4 v = make_float4(0.f, 0.f, 0.f, 0.f);
        if (row < NN) v = reinterpret_cast<const float4*>(X + (size_t)row * FIN)[lane];
        xs[wip][r][lane] = v;
    }
    __syncwarp();

    unsigned long long acc[R][NC];
    #pragma unroll
    for (int r = 0; r < R; r++)
        #pragma unroll
        for (int c = 0; c < NC; c++) acc[r][c] = 0ull;

    #pragma unroll 4
    for (int k4 = 0; k4 < FIN / 4; k4++) {
        unsigned long long wA[NC], wB[NC];
        #pragma unroll
        for (int c = 0; c < NC; c++) {
            uint2 hq = Wh[k4 * FOUT + c * 32 + lane];   // one LDG.64: 4 K-values
            wA[c] = f2_to_ull(__half22float2(*reinterpret_cast<__half2*>(&hq.x)));
            wB[c] = f2_to_ull(__half22float2(*reinterpret_cast<__half2*>(&hq.y)));
        }
        #pragma unroll
        for (int r = 0; r < R; r++) {
            ulonglong2 xv = reinterpret_cast<const ulonglong2*>(&xs[wip][r][0])[k4];
            #pragma unroll
            for (int c = 0; c < NC; c++) {
                ffma2(acc[r][c], wA[c], xv.x);
                ffma2(acc[r][c], wB[c], xv.y);
            }
        }
    }

    float asv[NC], adv[NC];
    #pragma unroll
    for (int c = 0; c < NC; c++) {
        asv[c] = a_s[c * 32 + lane];
        adv[c] = a_d[c * 32 + lane];
    }

    __half* __restrict__ hw16 = reinterpret_cast<__half*>(g_hwh);
    #pragma unroll
    for (int r = 0; r < R; r++) {
        int row = base + r;
        #pragma unroll
        for (int c = 0; c < NC; c++) {
            unsigned long long a = acc[r][c];
            float h = __uint_as_float((unsigned)(a & 0xffffffffull)) +
                      __uint_as_float((unsigned)(a >> 32));
            if (row < NN) hw16[(size_t)row * FOUT + c * 32 + lane] = __float2half_rn(h);
            float vs = h * asv[c], vd = h * adv[c];
            #pragma unroll
            for (int off = 16; off; off >>= 1) {
                vs += __shfl_xor_sync(0xffffffffu, vs, off);
                vd += __shfl_xor_sync(0xffffffffu, vd, off);
            }
            if (lane == 0 && row < NN) {
                g_asrc[row * HEADS_T + c] = vs;
                g_adst[row * HEADS_T + c] = vd;
            }
        }
    }
}

// ---------------- layers 1&2: one warp per dst, ALL 4 heads ----------------
// Parallel phase: lane = edgeSlot*4 + head (8 edges/chunk). Serial phase:
// shuffle-broadcast (weight, row offset); fixed 8-iter body, LDG.64 fp16
// gathers. Invalid tail edges: weight 0, source clamped. No-max softmax:
// logits bounded (~|l|<6) by input scaling.
__global__ void k_agg4(const float* __restrict__ bias) {
    int wip = threadIdx.x >> 5, lane = threadIdx.x & 31;
    int dst = blockIdx.x * 8 + wip;
    if (dst >= NN) return;

    int sub = lane & 3;          // head in parallel phase
    int ej  = lane >> 2;         // edge slot (0..7)
    int myhead = lane >> 3;      // head owning this lane's 4 channels

    float adv = g_adst[dst * HH + sub];
    int p0 = g_rowptr[dst], p1 = g_rowptr[dst + 1];

    float4 acc = make_float4(0.f, 0.f, 0.f, 0.f);
    float ssum = 0.f;
    const __half2* __restrict__ hp = g_hwh;

    for (int b = p0; b < p1; b += 8) {
        int p = b + ej;
        bool valid = (p < p1);
        int src = g_colidx[valid ? p : (p1 - 1)];   // clamp: always a real row
        float t = g_asrc[src * HH + sub] + adv;
        t = (t >= 0.f) ? t : NEG_SLOPE * t;
        float e = valid ? __expf(t) : 0.f;
        int offs = src * (DIM / 2);                 // half2 units
        ssum += e;

        float w[8]; int o[8];
        #pragma unroll
        for (int j = 0; j < 8; j++) {
            w[j] = __shfl_sync(0xffffffffu, e, j * 4 + myhead);
            o[j] = __shfl_sync(0xffffffffu, offs, j * 4);
        }
        #pragma unroll
        for (int j = 0; j < 8; j++) {
            uint2 raw = *reinterpret_cast<const uint2*>(hp + o[j] + lane * 2);
            float2 f0 = __half22float2(*reinterpret_cast<__half2*>(&raw.x));
            float2 f1 = __half22float2(*reinterpret_cast<__half2*>(&raw.y));
            acc.x += w[j] * f0.x; acc.y += w[j] * f0.y;
            acc.z += w[j] * f1.x; acc.w += w[j] * f1.y;
        }
    }
    // ssum per (ej,sub) -> reduce over edge slots (lane bits 2..4)
    ssum += __shfl_xor_sync(0xffffffffu, ssum, 4);
    ssum += __shfl_xor_sync(0xffffffffu, ssum, 8);
    ssum += __shfl_xor_sync(0xffffffffu, ssum, 16);
    float s = __shfl_sync(0xffffffffu, ssum, myhead);
    float inv = 1.f / (s + 1e-16f);

    float4 bb = *reinterpret_cast<const float4*>(bias + lane * 4);
    float4 o4;
    o4.x = acc.x * inv + bb.x;
    o4.y = acc.y * inv + bb.y;
    o4.z = acc.z * inv + bb.z;
    o4.w = acc.w * inv + bb.w;
    o4.x = (o4.x > 0.f) ? o4.x : expm1f(o4.x);   // ELU
    o4.y = (o4.y > 0.f) ? o4.y : expm1f(o4.y);
    o4.z = (o4.z > 0.f) ? o4.z : expm1f(o4.z);
    o4.w = (o4.w > 0.f) ? o4.w : expm1f(o4.w);
    *reinterpret_cast<float4*>(g_h + dst * DIM + lane * 4) = o4;
}

// ---------------- layer 3: warp per dst, single head, write out ----------
__global__ void k_agg1(const float* __restrict__ bias, float* __restrict__ OUT) {
    int wip = threadIdx.x >> 5, lane = threadIdx.x & 31;
    int dst = blockIdx.x * 8 + wip;
    if (dst >= NN) return;

    float adv = g_adst[dst];
    int p0 = g_rowptr[dst], p1 = g_rowptr[dst + 1];
    const __half* __restrict__ hw16 = reinterpret_cast<const __half*>(g_hwh);

    float ssum = 0.f;
    float acc = 0.f;
    for (int b = p0; b < p1; b += 32) {
        int p = b + lane;
        bool valid = (p < p1);
        int src = g_colidx[valid ? p : (p1 - 1)];
        float t = g_asrc[src] + adv;
        t = (t >= 0.f) ? t : NEG_SLOPE * t;
        float e = valid ? __expf(t) : 0.f;
        int offs = src * CC;
        ssum += e;

        int cnt = min(32, p1 - b);
        #pragma unroll
        for (int g = 0; g < 4; g++) {
            if (g * 8 >= cnt) break;            // uniform across warp
            float w[8]; int o[8];
            #pragma unroll
            for (int j = 0; j < 8; j++) {
                w[j] = __shfl_sync(0xffffffffu, e, g * 8 + j);
                o[j] = __shfl_sync(0xffffffffu, offs, g * 8 + j);
            }
            #pragma unroll
            for (int j = 0; j < 8; j++)
                acc += w[j] * __half2float(hw16[o[j] + lane]);
        }
    }
    float s = ssum;
    #pragma unroll
    for (int off = 16; off; off >>= 1)
        s += __shfl_xor_sync(0xffffffffu, s, off);

    OUT[dst * CC + lane] = acc / (s + 1e-16f) + bias[lane];
}

// ---------------- launch ----------------
extern "C" void kernel_launch(void* const* d_in, const int* in_sizes, int n_in,
                              void* d_out, int out_size) {
    const float* x   = (const float*)d_in[0];
    const int*   ei  = (const int*)  d_in[1];
    const float* W1  = (const float*)d_in[2];
    const float* as1 = (const float*)d_in[3];
    const float* ad1 = (const float*)d_in[4];
    const float* b1  = (const float*)d_in[5];
    const float* W2  = (const float*)d_in[6];
    const float* as2 = (const float*)d_in[7];
    const float* ad2 = (const float*)d_in[8];
    const float* b2  = (const float*)d_in[9];
    const float* W3  = (const float*)d_in[10];
    const float* as3 = (const float*)d_in[11];
    const float* ad3 = (const float*)d_in[12];
    const float* b3  = (const float*)d_in[13];
    float* out = (float*)d_out;

    static bool init = false;
    static void* cnt_ptr;
    static uint2 *wh1, *wh2, *wh3;
    if (!init) {
        cudaGetSymbolAddress(&cnt_ptr, g_count);
        cudaGetSymbolAddress((void**)&wh1, g_Wh1);
        cudaGetSymbolAddress((void**)&wh2, g_Wh2);
        cudaGetSymbolAddress((void**)&wh3, g_Wh3);
        init = true;
    }

    // CSR by destination (self-loops folded into scan)
    cudaMemsetAsync(cnt_ptr, 0, NN * sizeof(int));
    k_count<<<(EE + 255) / 256, 256>>>(ei);
    k_scan<<<1, 1024>>>();
    k_fill<<<(ETOT + 255) / 256, 256>>>(ei);

    const int gemm_blocks = (NN + 31) / 32;
    const int agg_blocks = (NN + 7) / 8;
    const int pack_blocks = ((DIM / 4) * DIM + (DIM / 4) * CC + 255) / 256;

    k_packAll<<<pack_blocks, 256>>>(W1, W2, W3);

    // layer 1
    k_gemm<DIM, DIM, HH, false><<<gemm_blocks, 128>>>(x, wh1, as1, ad1);
    k_agg4<<<agg_blocks, 256>>>(b1);

    // layer 2
    k_gemm<DIM, DIM, HH, true><<<gemm_blocks, 128>>>(nullptr, wh2, as2, ad2);
    k_agg4<<<agg_blocks, 256>>>(b2);

    // layer 3
    k_gemm<DIM, CC, 1, true><<<gemm_blocks, 128>>>(nullptr, wh3, as3, ad3);
    k_agg1<<<agg_blocks, 256>>>(b3, out);
}

// round 17
// speedup vs baseline: 1.1905x; 1.0292x over previous
#include <cuda_runtime.h>
#include <cuda_fp16.h>
#include <math.h>

#define NN 50000
#define EE 800000
#define ETOT (EE + NN)
#define DIM 128
#define HH 4
#define CC 32
#define NEG_SLOPE 0.2f

// ---------------- device scratch (no allocations allowed) ----------------
__device__ int     g_count[NN];
__device__ int     g_rowptr[NN + 1];
__device__ int     g_cursor[NN];
__device__ int     g_colidx[ETOT];
__device__ float   g_h[NN * DIM];          // activated layer input, fp32
__device__ __half2 g_hwh[NN * (DIM / 2)];  // transformed features, fp16 gather array
__device__ float   g_asrc[NN * HH];
__device__ float   g_adst[NN * HH];
// fp16 K-quad packed weights: [k4*FOUT + j] = {h2(W[4k4][j],W[4k4+1][j]), h2(W[4k4+2][j],W[4k4+3][j])}
__device__ uint2   g_Wh1[(DIM / 4) * DIM];
__device__ uint2   g_Wh2[(DIM / 4) * DIM];
__device__ uint2   g_Wh3[(DIM / 4) * CC];

// ---------------- CSR build ----------------
__global__ void k_count(const int* __restrict__ ei) {
    int e = blockIdx.x * blockDim.x + threadIdx.x;
    if (e < EE) atomicAdd(&g_count[ei[EE + e]], 1);
}

// single-block shuffle-based exclusive scan (N=50000); +1 folds in self loop
__global__ void k_scan() {
    __shared__ int wsum[32];
    __shared__ int carry_s;
    int lane = threadIdx.x & 31;
    int wid  = threadIdx.x >> 5;
    if (threadIdx.x == 0) carry_s = 0;
    __syncthreads();
    for (int base = 0; base < NN; base += 1024) {
        int i = base + threadIdx.x;
        int v = (i < NN) ? (g_count[i] + 1) : 0;   // +1 = self loop
        int x = v;
        #pragma unroll
        for (int off = 1; off < 32; off <<= 1) {
            int t = __shfl_up_sync(0xffffffffu, x, off);
            if (lane >= off) x += t;
        }
        if (lane == 31) wsum[wid] = x;
        __syncthreads();
        if (wid == 0) {
            int y = wsum[lane];
            #pragma unroll
            for (int off = 1; off < 32; off <<= 1) {
                int t = __shfl_up_sync(0xffffffffu, y, off);
                if (lane >= off) y += t;
            }
            wsum[lane] = y;
        }
        __syncthreads();
        int wpre = (wid > 0) ? wsum[wid - 1] : 0;
        int excl = carry_s + wpre + x - v;
        if (i < NN) { g_rowptr[i] = excl; g_cursor[i] = excl; }
        int tot = wsum[31];
        __syncthreads();
        if (threadIdx.x == 0) carry_s += tot;
        __syncthreads();
    }
    if (threadIdx.x == 0) g_rowptr[NN] = carry_s;
}

__global__ void k_fill(const int* __restrict__ ei) {
    int e = blockIdx.x * blockDim.x + threadIdx.x;
    if (e < EE) {
        int d = ei[EE + e];
        int pos = atomicAdd(&g_cursor[d], 1);
        g_colidx[pos] = ei[e];
    } else if (e < EE + NN) {
        int i = e - EE;
        int pos = atomicAdd(&g_cursor[i], 1);
        g_colidx[pos] = i;    // self loop
    }
}

// ---------------- pack ALL weight matrices to fp16 K-quads (one launch) ----
__device__ __forceinline__ uint2 packquad(const float* W, int k4, int j, int FOUT) {
    __half2 lo = __floats2half2_rn(W[(4 * k4) * FOUT + j], W[(4 * k4 + 1) * FOUT + j]);
    __half2 hi = __floats2half2_rn(W[(4 * k4 + 2) * FOUT + j], W[(4 * k4 + 3) * FOUT + j]);
    uint2 r;
    r.x = *reinterpret_cast<unsigned*>(&lo);
    r.y = *reinterpret_cast<unsigned*>(&hi);
    return r;
}

__global__ void k_packAll(const float* __restrict__ W1, const float* __restrict__ W2,
                          const float* __restrict__ W3) {
    int i = blockIdx.x * blockDim.x + threadIdx.x;
    if (i < (DIM / 4) * DIM) {
        int k4 = i / DIM, j = i - k4 * DIM;
        g_Wh1[i] = packquad(W1, k4, j, DIM);
        g_Wh2[i] = packquad(W2, k4, j, DIM);
    } else {
        int t = i - (DIM / 4) * DIM;
        if (t < (DIM / 4) * CC) {
            int k4 = t / CC, j = t - k4 * CC;
            g_Wh3[t] = packquad(W3, k4, j, CC);
        }
    }
}

__device__ __forceinline__ void ffma2(unsigned long long& d,
                                      unsigned long long a, unsigned long long b) {
    asm("fma.rn.f32x2 %0, %1, %2, %0;" : "+l"(d) : "l"(a), "l"(b));
}

__device__ __forceinline__ unsigned long long f2_to_ull(float2 f) {
    unsigned long long u;
    asm("mov.b64 %0, {%1, %2};" : "=l"(u) : "f"(f.x), "f"(f.y));
    return u;
}

// ---------------- GEMM + attention-coefficient reduction ----------------
// fp32 math, fp16 weights (converted in registers); h stored fp16, logits fp32.
template <int FIN, int FOUT, int HEADS_T, bool USE_GH>
__global__ void k_gemm(const float* __restrict__ Xin, const uint2* __restrict__ Wh,
                       const float* __restrict__ a_s, const float* __restrict__ a_d) {
    const int R = 8;
    const int NC = FOUT / 32;
    __shared__ float4 xs[4][R][FIN / 4];
    int lane = threadIdx.x & 31, wip = threadIdx.x >> 5;
    int base = (blockIdx.x * 4 + wip) * R;
    const float* __restrict__ X = USE_GH ? (const float*)g_h : Xin;

    #pragma unroll
    for (int r = 0; r < R; r++) {
        int row = base + r;
        float4 v = make_float4(0.f, 0.f, 0.f, 0.f);
        if (row < NN) v = reinterpret_cast<const float4*>(X + (size_t)row * FIN)[lane];
        xs[wip][r][lane] = v;
    }
    __syncwarp();

    unsigned long long acc[R][NC];
    #pragma unroll
    for (int r = 0; r < R; r++)
        #pragma unroll
        for (int c = 0; c < NC; c++) acc[r][c] = 0ull;

    #pragma unroll 4
    for (int k4 = 0; k4 < FIN / 4; k4++) {
        unsigned long long wA[NC], wB[NC];
        #pragma unroll
        for (int c = 0; c < NC; c++) {
            uint2 hq = Wh[k4 * FOUT + c * 32 + lane];   // one LDG.64: 4 K-values
            wA[c] = f2_to_ull(__half22float2(*reinterpret_cast<__half2*>(&hq.x)));
            wB[c] = f2_to_ull(__half22float2(*reinterpret_cast<__half2*>(&hq.y)));
        }
        #pragma unroll
        for (int r = 0; r < R; r++) {
            ulonglong2 xv = reinterpret_cast<const ulonglong2*>(&xs[wip][r][0])[k4];
            #pragma unroll
            for (int c = 0; c < NC; c++) {
                ffma2(acc[r][c], wA[c], xv.x);
                ffma2(acc[r][c], wB[c], xv.y);
            }
        }
    }

    float asv[NC], adv[NC];
    #pragma unroll
    for (int c = 0; c < NC; c++) {
        asv[c] = a_s[c * 32 + lane];
        adv[c] = a_d[c * 32 + lane];
    }

    __half* __restrict__ hw16 = reinterpret_cast<__half*>(g_hwh);
    #pragma unroll
    for (int r = 0; r < R; r++) {
        int row = base + r;
        #pragma unroll
        for (int c = 0; c < NC; c++) {
            unsigned long long a = acc[r][c];
            float h = __uint_as_float((unsigned)(a & 0xffffffffull)) +
                      __uint_as_float((unsigned)(a >> 32));
            if (row < NN) hw16[(size_t)row * FOUT + c * 32 + lane] = __float2half_rn(h);
            float vs = h * asv[c], vd = h * adv[c];
            #pragma unroll
            for (int off = 16; off; off >>= 1) {
                vs += __shfl_xor_sync(0xffffffffu, vs, off);
                vd += __shfl_xor_sync(0xffffffffu, vd, off);
            }
            if (lane == 0 && row < NN) {
                g_asrc[row * HEADS_T + c] = vs;
                g_adst[row * HEADS_T + c] = vd;
            }
        }
    }
}

// ---------------- layers 1&2: one warp per dst, ALL 4 heads ----------------
__global__ void k_agg4(const float* __restrict__ bias) {
    int wip = threadIdx.x >> 5, lane = threadIdx.x & 31;
    int dst = blockIdx.x * 8 + wip;
    if (dst >= NN) return;

    int sub = lane & 3;          // head in parallel phase
    int ej  = lane >> 2;         // edge slot (0..7)
    int myhead = lane >> 3;      // head owning this lane's 4 channels

    float adv = g_adst[dst * HH + sub];
    int p0 = g_rowptr[dst], p1 = g_rowptr[dst + 1];

    float4 acc = make_float4(0.f, 0.f, 0.f, 0.f);
    float ssum = 0.f;
    const __half2* __restrict__ hp = g_hwh;

    for (int b = p0; b < p1; b += 8) {
        int p = b + ej;
        bool valid = (p < p1);
        int src = g_colidx[valid ? p : (p1 - 1)];   // clamp: always a real row
        float t = g_asrc[src * HH + sub] + adv;
        t = (t >= 0.f) ? t : NEG_SLOPE * t;
        float e = valid ? __expf(t) : 0.f;
        int offs = src * (DIM / 2);                 // half2 units
        ssum += e;

        float w[8]; int o[8];
        #pragma unroll
        for (int j = 0; j < 8; j++) {
            w[j] = __shfl_sync(0xffffffffu, e, j * 4 + myhead);
            o[j] = __shfl_sync(0xffffffffu, offs, j * 4);
        }
        #pragma unroll
        for (int j = 0; j < 8; j++) {
            uint2 raw = *reinterpret_cast<const uint2*>(hp + o[j] + lane * 2);
            float2 f0 = __half22float2(*reinterpret_cast<__half2*>(&raw.x));
            float2 f1 = __half22float2(*reinterpret_cast<__half2*>(&raw.y));
            acc.x += w[j] * f0.x; acc.y += w[j] * f0.y;
            acc.z += w[j] * f1.x; acc.w += w[j] * f1.y;
        }
    }
    ssum += __shfl_xor_sync(0xffffffffu, ssum, 4);
    ssum += __shfl_xor_sync(0xffffffffu, ssum, 8);
    ssum += __shfl_xor_sync(0xffffffffu, ssum, 16);
    float s = __shfl_sync(0xffffffffu, ssum, myhead);
    float inv = 1.f / (s + 1e-16f);

    float4 bb = *reinterpret_cast<const float4*>(bias + lane * 4);
    float4 o4;
    o4.x = acc.x * inv + bb.x;
    o4.y = acc.y * inv + bb.y;
    o4.z = acc.z * inv + bb.z;
    o4.w = acc.w * inv + bb.w;
    o4.x = (o4.x > 0.f) ? o4.x : expm1f(o4.x);   // ELU
    o4.y = (o4.y > 0.f) ? o4.y : expm1f(o4.y);
    o4.z = (o4.z > 0.f) ? o4.z : expm1f(o4.z);
    o4.w = (o4.w > 0.f) ? o4.w : expm1f(o4.w);
    *reinterpret_cast<float4*>(g_h + dst * DIM + lane * 4) = o4;
}

// ---------------- layer 3: warp per dst, single head, write out ----------
__global__ void k_agg1(const float* __restrict__ bias, float* __restrict__ OUT) {
    int wip = threadIdx.x >> 5, lane = threadIdx.x & 31;
    int dst = blockIdx.x * 8 + wip;
    if (dst >= NN) return;

    float adv = g_adst[dst];
    int p0 = g_rowptr[dst], p1 = g_rowptr[dst + 1];
    const __half* __restrict__ hw16 = reinterpret_cast<const __half*>(g_hwh);

    float ssum = 0.f;
    float acc = 0.f;
    for (int b = p0; b < p1; b += 32) {
        int p = b + lane;
        bool valid = (p < p1);
        int src = g_colidx[valid ? p : (p1 - 1)];
        float t = g_asrc[src] + adv;
        t = (t >= 0.f) ? t : NEG_SLOPE * t;
        float e = valid ? __expf(t) : 0.f;
        int offs = src * CC;
        ssum += e;

        int cnt = min(32, p1 - b);
        #pragma unroll
        for (int g = 0; g < 4; g++) {
            if (g * 8 >= cnt) break;            // uniform across warp
            float w[8]; int o[8];
            #pragma unroll
            for (int j = 0; j < 8; j++) {
                w[j] = __shfl_sync(0xffffffffu, e, g * 8 + j);
                o[j] = __shfl_sync(0xffffffffu, offs, g * 8 + j);
            }
            #pragma unroll
            for (int j = 0; j < 8; j++)
                acc += w[j] * __half2float(hw16[o[j] + lane]);
        }
    }
    float s = ssum;
    #pragma unroll
    for (int off = 16; off; off >>= 1)
        s += __shfl_xor_sync(0xffffffffu, s, off);

    OUT[dst * CC + lane] = acc / (s + 1e-16f) + bias[lane];
}

// ---------------- launch ----------------
extern "C" void kernel_launch(void* const* d_in, const int* in_sizes, int n_in,
                              void* d_out, int out_size) {
    const float* x   = (const float*)d_in[0];
    const int*   ei  = (const int*)  d_in[1];
    const float* W1  = (const float*)d_in[2];
    const float* as1 = (const float*)d_in[3];
    const float* ad1 = (const float*)d_in[4];
    const float* b1  = (const float*)d_in[5];
    const float* W2  = (const float*)d_in[6];
    const float* as2 = (const float*)d_in[7];
    const float* ad2 = (const float*)d_in[8];
    const float* b2  = (const float*)d_in[9];
    const float* W3  = (const float*)d_in[10];
    const float* as3 = (const float*)d_in[11];
    const float* ad3 = (const float*)d_in[12];
    const float* b3  = (const float*)d_in[13];
    float* out = (float*)d_out;

    static bool init = false;
    static cudaStream_t s2;
    static cudaEvent_t evA, evB;
    static void* cnt_ptr;
    static uint2 *wh1, *wh2, *wh3;
    if (!init) {
        cudaStreamCreateWithFlags(&s2, cudaStreamNonBlocking);
        cudaEventCreateWithFlags(&evA, cudaEventDisableTiming);
        cudaEventCreateWithFlags(&evB, cudaEventDisableTiming);
        cudaGetSymbolAddress(&cnt_ptr, g_count);
        cudaGetSymbolAddress((void**)&wh1, g_Wh1);
        cudaGetSymbolAddress((void**)&wh2, g_Wh2);
        cudaGetSymbolAddress((void**)&wh3, g_Wh3);
        init = true;
    }

    const int gemm_blocks = (NN + 31) / 32;
    const int agg_blocks = (NN + 7) / 8;
    const int pack_blocks = ((DIM / 4) * DIM + (DIM / 4) * CC + 255) / 256;

    // ---- fork: CSR build on s2, pack + gemm1 on main ----
    cudaEventRecord(evA, 0);
    cudaStreamWaitEvent(s2, evA, 0);

    cudaMemsetAsync(cnt_ptr, 0, NN * sizeof(int), s2);
    k_count<<<(EE + 255) / 256, 256, 0, s2>>>(ei);
    k_scan<<<1, 1024, 0, s2>>>();
    k_fill<<<(ETOT + 255) / 256, 256, 0, s2>>>(ei);
    cudaEventRecord(evB, s2);

    k_packAll<<<pack_blocks, 256>>>(W1, W2, W3);
    k_gemm<DIM, DIM, HH, false><<<gemm_blocks, 128>>>(x, wh1, as1, ad1);

    // ---- join: aggregation needs CSR + gemm1 ----
    cudaStreamWaitEvent(0, evB, 0);

    // layer 1
    k_agg4<<<agg_blocks, 256>>>(b1);

    // layer 2
    k_gemm<DIM, DIM, HH, true><<<gemm_blocks, 128>>>(nullptr, wh2, as2, ad2);
    k_agg4<<<agg_blocks, 256>>>(b2);

    // layer 3
    k_gemm<DIM, CC, 1, true><<<gemm_blocks, 128>>>(nullptr, wh3, as3, ad3);
    k_agg1<<<agg_blocks, 256>>>(b3, out);
}